// round 11
// baseline (speedup 1.0000x reference)
#include <cuda_runtime.h>
#include <math_constants.h>

#define NB 4
#define NN 16384
#define NM 512
#define NC 128
#define NK 16
#define NL 6
#define NSTEPS 5
#define GG 32
#define G3 (GG*GG*GG)
#define NCH 256
#define CHSZ 64

// ---------------- scratch (device globals: no allocations allowed) ----------
__device__ float g_feats[NB*NN*NC];
__device__ float g_Qf[NB*NN*NC];
__device__ float g_Gf[NB*NN*NC];
__device__ __align__(16) float g_pos4[NB*NN*4];
__device__ float g_wsel[NB*NM*NL*NC];
__device__ float g_rout[2][NB*NM*NL*NC];
__device__ float g_disp[NB*NM*3];
__device__ unsigned g_bboxi[NB][6];
__device__ __align__(16) int g_cellcnt[NB][G3];
__device__ __align__(16) float4 g_spos[NB*NN];   // morton-sorted, .w = orig idx bits
__device__ int g_slot[NB*NN];                    // orig idx -> sorted slot
__device__ __align__(16) float4 g_cbbmn[NB*NCH]; // per-chunk bbox min
__device__ __align__(16) float4 g_cbbmx[NB*NCH]; // per-chunk bbox max

// ---------------- f32x2 packed helpers --------------------------------------
__device__ __forceinline__ void dfma2(unsigned long long& d,
                                      unsigned long long a,
                                      unsigned long long b) {
    asm("fma.rn.f32x2 %0, %1, %2, %0;" : "+l"(d) : "l"(a), "l"(b));
}
__device__ __forceinline__ unsigned long long packdup(float w) {
    unsigned long long r;
    asm("mov.b64 %0, {%1, %1};" : "=l"(r) : "f"(w));
    return r;
}
__device__ __forceinline__ void unpack2(unsigned long long a, float& lo, float& hi) {
    asm("mov.b64 {%0, %1}, %2;" : "=f"(lo), "=f"(hi) : "l"(a));
}

// ---------------- order-preserving float<->uint encoding --------------------
__device__ __forceinline__ unsigned encf(float f) {
    int i = __float_as_int(f);
    return (i >= 0) ? ((unsigned)i | 0x80000000u) : ~(unsigned)i;
}
__device__ __forceinline__ float decf(unsigned k) {
    return __int_as_float((k & 0x80000000u) ? (int)(k ^ 0x80000000u) : (int)~k);
}

struct BBox { float mnx, mny, mnz, ivx, ivy, ivz; };
__device__ __forceinline__ BBox load_bbox(int b) {
    BBox bb;
    bb.mnx = decf(g_bboxi[b][0]); bb.mny = decf(g_bboxi[b][1]); bb.mnz = decf(g_bboxi[b][2]);
    float rx = fmaxf(decf(g_bboxi[b][3]) - bb.mnx, 1e-6f);
    float ry = fmaxf(decf(g_bboxi[b][4]) - bb.mny, 1e-6f);
    float rz = fmaxf(decf(g_bboxi[b][5]) - bb.mnz, 1e-6f);
    bb.ivx = (float)GG / rx; bb.ivy = (float)GG / ry; bb.ivz = (float)GG / rz;
    return bb;
}
__device__ __forceinline__ int clampg(int v) { return min(GG-1, max(0, v)); }
__device__ __forceinline__ unsigned part1by2(unsigned x) {
    x &= 0x3ffu;
    x = (x | (x << 16)) & 0x30000ffu;
    x = (x | (x << 8))  & 0x300f00fu;
    x = (x | (x << 4))  & 0x30c30c3u;
    x = (x | (x << 2))  & 0x9249249u;
    return x;
}
__device__ __forceinline__ int cell_of(const BBox& bb, float x, float y, float z) {
    int cx = clampg((int)((x - bb.mnx) * bb.ivx));
    int cy = clampg((int)((y - bb.mny) * bb.ivy));
    int cz = clampg((int)((z - bb.mnz) * bb.ivz));
    return (int)(part1by2((unsigned)cx) | (part1by2((unsigned)cy) << 1)
                 | (part1by2((unsigned)cz) << 2));
}
__device__ __forceinline__ void bbox_reset(int gid) {
    if (gid < NB*6) ((unsigned*)g_bboxi)[gid] = (gid % 6) < 3 ? 0xFFFFFFFFu : 0u;
}

// ---------------- init ------------------------------------------------------
__global__ void init_pos_kernel(const float* __restrict__ xyz) {
    int i = blockIdx.x * blockDim.x + threadIdx.x;
    bbox_reset(i);
    if (i < NB*NN) {
        float x = xyz[i*3+0], y = xyz[i*3+1], z = xyz[i*3+2];
        *(float4*)&g_pos4[(size_t)i*4] = make_float4(x, y, z, 0.f);
    }
}

// ---------------- grid prep: zero histogram + bbox atomic reduce ------------
__global__ void gridprep_kernel() {
    __shared__ unsigned smn[3][8], smx[3][8];
    int tid = threadIdx.x;
    int gid = blockIdx.x * 256 + tid;           // 65536 threads
    if (gid < NB*G3/4) ((int4*)g_cellcnt)[gid] = make_int4(0,0,0,0);
    int b = blockIdx.x >> 6;
    int i = (blockIdx.x & 63) * 256 + tid;
    const float4 p = *(const float4*)&g_pos4[((size_t)b*NN + i) * 4];
    unsigned ex = encf(p.x), ey = encf(p.y), ez = encf(p.z);
    unsigned nx = ex, ny = ey, nz = ez;
    #pragma unroll
    for (int off = 16; off; off >>= 1) {
        nx = min(nx, __shfl_xor_sync(0xffffffffu, nx, off));
        ny = min(ny, __shfl_xor_sync(0xffffffffu, ny, off));
        nz = min(nz, __shfl_xor_sync(0xffffffffu, nz, off));
        ex = max(ex, __shfl_xor_sync(0xffffffffu, ex, off));
        ey = max(ey, __shfl_xor_sync(0xffffffffu, ey, off));
        ez = max(ez, __shfl_xor_sync(0xffffffffu, ez, off));
    }
    int warp = tid >> 5;
    if ((tid & 31) == 0) {
        smn[0][warp] = nx; smn[1][warp] = ny; smn[2][warp] = nz;
        smx[0][warp] = ex; smx[1][warp] = ey; smx[2][warp] = ez;
    }
    __syncthreads();
    if (tid < 3) {
        unsigned mn = 0xFFFFFFFFu, mx = 0u;
        #pragma unroll
        for (int w = 0; w < 8; w++) { mn = min(mn, smn[tid][w]); mx = max(mx, smx[tid][w]); }
        atomicMin(&g_bboxi[b][tid], mn);
        atomicMax(&g_bboxi[b][tid + 3], mx);
    }
}

__global__ void hist_kernel() {
    int gid = blockIdx.x * 256 + threadIdx.x;
    int b = gid >> 14, i = gid & (NN-1);
    BBox bb = load_bbox(b);
    const float4 p = *(const float4*)&g_pos4[((size_t)b*NN + i) * 4];
    int c = cell_of(bb, p.x, p.y, p.z);
    atomicAdd(&g_cellcnt[b][c], 1);
}

// exclusive scan over G3 morton cells (1 block / batch, 1024 thr, 32 cells ea)
__global__ void scan_kernel() {
    __shared__ int ss[1024];
    int b = blockIdx.x, t = threadIdx.x;
    int base = t * 32;
    int4* cn4 = (int4*)&g_cellcnt[b][base];
    int4 v[8];
    int s = 0;
    #pragma unroll
    for (int k = 0; k < 8; k++) { v[k] = cn4[k]; s += v[k].x + v[k].y + v[k].z + v[k].w; }
    int mysum = s;
    ss[t] = s; __syncthreads();
    for (int off = 1; off < 1024; off <<= 1) {
        int q = (t >= off) ? ss[t - off] : 0;
        __syncthreads();
        ss[t] += q;
        __syncthreads();
    }
    int running = ss[t] - mysum;
    #pragma unroll
    for (int k = 0; k < 8; k++) {
        int4 w;
        w.x = running; running += v[k].x;
        w.y = running; running += v[k].y;
        w.z = running; running += v[k].z;
        w.w = running; running += v[k].w;
        cn4[k] = w;
    }
}

__global__ void scatterpts_kernel() {
    int gid = blockIdx.x * 256 + threadIdx.x;
    int b = gid >> 14, i = gid & (NN-1);
    BBox bb = load_bbox(b);
    const float4 p = *(const float4*)&g_pos4[((size_t)b*NN + i) * 4];
    int c = cell_of(bb, p.x, p.y, p.z);
    int slot = atomicAdd(&g_cellcnt[b][c], 1);
    g_spos[(size_t)b*NN + slot] = make_float4(p.x, p.y, p.z, __int_as_float(i));
    g_slot[(size_t)b*NN + i] = slot;
}

// per-chunk bbox: 1024 warps, one chunk each
__global__ void chunkbb_kernel() {
    int gt = blockIdx.x * blockDim.x + threadIdx.x;
    int w = gt >> 5, lane = gt & 31;
    int b = w >> 8, ck = w & 255;
    const float4* sp4 = g_spos + (size_t)b*NN;
    float4 pA = sp4[ck*CHSZ + lane];
    float4 pB = sp4[ck*CHSZ + 32 + lane];
    float mnx = fminf(pA.x, pB.x), mxx = fmaxf(pA.x, pB.x);
    float mny = fminf(pA.y, pB.y), mxy = fmaxf(pA.y, pB.y);
    float mnz = fminf(pA.z, pB.z), mxz = fmaxf(pA.z, pB.z);
    #pragma unroll
    for (int off = 16; off; off >>= 1) {
        mnx = fminf(mnx, __shfl_xor_sync(0xffffffffu, mnx, off));
        mny = fminf(mny, __shfl_xor_sync(0xffffffffu, mny, off));
        mnz = fminf(mnz, __shfl_xor_sync(0xffffffffu, mnz, off));
        mxx = fmaxf(mxx, __shfl_xor_sync(0xffffffffu, mxx, off));
        mxy = fmaxf(mxy, __shfl_xor_sync(0xffffffffu, mxy, off));
        mxz = fmaxf(mxz, __shfl_xor_sync(0xffffffffu, mxz, off));
    }
    if (lane == 0) {
        g_cbbmn[w] = make_float4(mnx, mny, mnz, 0.f);
        g_cbbmx[w] = make_float4(mxx, mxy, mxz, 0.f);
    }
}

// ---------------- encoder ---------------------------------------------------
__global__ void encode_kernel(const float* __restrict__ xyz,
                              const float* __restrict__ w1, const float* __restrict__ b1,
                              const float* __restrict__ w2, const float* __restrict__ b2) {
    __shared__ float h[4][64];
    int tid = threadIdx.x;
    int p0 = blockIdx.x * 4;
    for (int i = tid; i < 4*64; i += 128) {
        int pt = i >> 6, j = i & 63;
        const float* x = xyz + (size_t)(p0 + pt) * 3;
        float v = b1[j] + w1[j*3+0]*x[0] + w1[j*3+1]*x[1] + w1[j*3+2]*x[2];
        h[pt][j] = fmaxf(v, 0.f);
    }
    __syncthreads();
    float acc[4];
    #pragma unroll
    for (int p = 0; p < 4; p++) acc[p] = b2[tid];
    const float4* wr = (const float4*)(w2 + (size_t)tid * 64);
    #pragma unroll
    for (int j4 = 0; j4 < 16; j4++) {
        float4 w = wr[j4];
        #pragma unroll
        for (int p = 0; p < 4; p++) {
            float4 hv = *(const float4*)&h[p][4*j4];
            acc[p] += w.x*hv.x + w.y*hv.y + w.z*hv.z + w.w*hv.w;
        }
    }
    #pragma unroll
    for (int p = 0; p < 4; p++)
        g_feats[(size_t)(p0 + p) * NC + tid] = acc[p];
}

// ---------------- beta/gamma projections (f32x2 point-pairs) ----------------
__global__ void proj_kernel(const float* __restrict__ bw, const float* __restrict__ bb,
                            const float* __restrict__ gw, const float* __restrict__ gb) {
    __shared__ __align__(8) float xs[128*16];      // xs[ch*16 + p]
    int c = threadIdx.x;                           // 128 threads
    size_t base = (size_t)blockIdx.x * 16 * 128;
    for (int i = c; i < 16*128; i += 128) {
        int p = i >> 7, ch = i & 127;
        xs[ch*16 + p] = g_feats[base + i];
    }
    __syncthreads();
    unsigned long long accQ[8], accG[8];
    unsigned long long bq = packdup(bb[c]), bg = packdup(gb[c]);
    #pragma unroll
    for (int p = 0; p < 8; p++) { accQ[p] = bq; accG[p] = bg; }
    const float4* wq = (const float4*)(bw + (size_t)c * 128);
    const float4* wg = (const float4*)(gw + (size_t)c * 128);
    for (int j4 = 0; j4 < 32; j4++) {
        float4 a = wq[j4];
        float4 g = wg[j4];
        float aa[4] = {a.x, a.y, a.z, a.w};
        float gg2[4] = {g.x, g.y, g.z, g.w};
        #pragma unroll
        for (int jj = 0; jj < 4; jj++) {
            int ch = 4*j4 + jj;
            unsigned long long wa = packdup(aa[jj]);
            unsigned long long wgv = packdup(gg2[jj]);
            const unsigned long long* x2 = (const unsigned long long*)&xs[ch*16];
            #pragma unroll
            for (int p = 0; p < 8; p++) {
                dfma2(accQ[p], x2[p], wa);
                dfma2(accG[p], x2[p], wgv);
            }
        }
    }
    #pragma unroll
    for (int p = 0; p < 8; p++) {
        float q0, q1, g0, g1;
        unpack2(accQ[p], q0, q1);
        unpack2(accG[p], g0, g1);
        g_Qf[base + (size_t)(2*p)*128 + c]   = q0;
        g_Qf[base + (size_t)(2*p+1)*128 + c] = q1;
        g_Gf[base + (size_t)(2*p)*128 + c]   = g0;
        g_Gf[base + (size_t)(2*p+1)*128 + c] = g1;
    }
}

// ---------------- KNN: warp-distributed sorted top-17 insert ----------------
__device__ __forceinline__ void kinsert(unsigned bal, float d, int ci,
                                        float& ld, int& li, float& tau, int lane) {
    do {
        int src = __ffs(bal) - 1; bal &= bal - 1;
        float dc = __shfl_sync(0xffffffffu, d, src);
        int   ic = __shfl_sync(0xffffffffu, ci, src);
        float pd = __shfl_up_sync(0xffffffffu, ld, 1);
        int   pi = __shfl_up_sync(0xffffffffu, li, 1);
        unsigned lt = __ballot_sync(0xffffffffu,
                (ld < dc) || ((ld == dc) && (li < ic))) & 0x1FFFFu;
        int pn = __popc(lt);
        if (lane < 17) {
            if (lane == pn)      { ld = dc; li = ic; }
            else if (lane > pn)  { ld = pd; li = pi; }
        }
    } while (bal);
    tau = __shfl_sync(0xffffffffu, ld, 16);
}

__device__ __forceinline__ void scan_chunk(const float4* __restrict__ sp4, int ck,
                                           float qx, float qy, float qz,
                                           float& ld, int& li, float& tau, int lane) {
    int j0 = ck*CHSZ + lane;
    float4 pA = __ldg(&sp4[j0]);
    float4 pB = __ldg(&sp4[j0 + 32]);
    float dxa = pA.x - qx, dya = pA.y - qy, dza = pA.z - qz;
    float dA = fmaf(dza, dza, fmaf(dya, dya, dxa*dxa));
    float dxb = pB.x - qx, dyb = pB.y - qy, dzb = pB.z - qz;
    float dB = fmaf(dzb, dzb, fmaf(dyb, dyb, dxb*dxb));
    int iA = __float_as_int(pA.w), iB = __float_as_int(pB.w);
    unsigned balA = __ballot_sync(0xffffffffu, dA < tau);
    if (balA) kinsert(balA, dA, iA, ld, li, tau, lane);
    unsigned balB = __ballot_sync(0xffffffffu, dB < tau);
    if (balB) kinsert(balB, dB, iB, ld, li, tau, lane);
}

// ---------------- fused per-step selector: chunked KNN + gumbel argmax -----
#define KWPB 8
__global__ __launch_bounds__(256)
void knn_step_kernel(const int* __restrict__ start,
                     const float* __restrict__ gumbel, int t) {
    __shared__ int sknn[KWPB][NK];
    int warp = threadIdx.x >> 5, lane = threadIdx.x & 31;
    int b = blockIdx.x / (NM/KWPB);
    int m = (blockIdx.x % (NM/KWPB)) * KWPB + warp;
    int gw = b*NM + m;
    int qidx = start[gw];
    const float4* pos = (const float4*)(g_pos4 + (size_t)b*NN*4);
    const float4* sp4 = g_spos + (size_t)b*NN;
    const float* Gf = g_Gf + (size_t)b*NN*NC;
    const float4* cbmn = g_cbbmn + b*NCH;
    const float4* cbmx = g_cbbmx + b*NCH;

    {   // walk[0] = feats[start]
        const float* fr = g_feats + ((size_t)b*NN + qidx) * NC;
        float* wr = g_wsel + (size_t)gw * NL * NC;
        #pragma unroll
        for (int r = 0; r < 4; r++) wr[lane + 32*r] = fr[lane + 32*r];
    }

    for (int l = 0; l < NL-1; l++) {
        float4 qp = pos[qidx];
        float qx = qp.x, qy = qp.y, qz = qp.z;
        float ld = CUDART_INF_F;
        int   li = 0x7FFFFFFF;
        float tau = CUDART_INF_F;
        int seedck = g_slot[(size_t)b*NN + qidx] >> 6;

        // seed: the chunk containing the query itself
        scan_chunk(sp4, seedck, qx, qy, qz, ld, li, tau, lane);

        // bbox-pruned pass over all other chunks (exact superset via margin)
        for (int cb0 = 0; cb0 < NCH; cb0 += 32) {
            int cb = cb0 + lane;
            float4 mn = __ldg(&cbmn[cb]);
            float4 mx = __ldg(&cbmx[cb]);
            float ex = fmaxf(fmaxf(mn.x - qx, qx - mx.x), 0.f);
            float ey = fmaxf(fmaxf(mn.y - qy, qy - mx.y), 0.f);
            float ez = fmaxf(fmaxf(mn.z - qz, qz - mx.z), 0.f);
            float bd = fmaf(ez, ez, fmaf(ey, ey, ex*ex));
            bool hit = (cb != seedck) && (bd <= tau * 1.00002f);
            unsigned bal = __ballot_sync(0xffffffffu, hit);
            while (bal) {
                int src = __ffs(bal) - 1; bal &= bal - 1;
                scan_chunk(sp4, cb0 + src, qx, qy, qz, ld, li, tau, lane);
            }
        }

        // lanes 0..16 = sorted top-17 (lex (d, idx)); lane0 = self
        if (lane >= 1 && lane < 17) sknn[warp][lane - 1] = li;
        __syncwarp();

        // logits + gumbel argmax
        const float* Q = g_Qf + ((size_t)b*NN + qidx) * NC;
        float qv0 = Q[lane], qv1 = Q[lane+32], qv2 = Q[lane+64], qv3 = Q[lane+96];
        float pk[16];
        #pragma unroll
        for (int k = 0; k < 16; k++) {
            const float* gr = Gf + (size_t)sknn[warp][k] * NC;
            pk[k] = qv0*gr[lane] + qv1*gr[lane+32] + qv2*gr[lane+64] + qv3*gr[lane+96];
        }
        #pragma unroll
        for (int k = 0; k < 16; k++) {
            #pragma unroll
            for (int off = 16; off; off >>= 1)
                pk[k] += __shfl_xor_sync(0xffffffffu, pk[k], off);
        }
        const float* gm = gumbel + ((((size_t)t*(NL-1) + l)*NB + b)*NM + m) * NK;
        float best = -CUDART_INF_F; int bk = 0;
        #pragma unroll
        for (int k = 0; k < 16; k++) {
            float s = pk[k] / 11.313708498984761f + gm[k];   // /sqrt(128)
            if (s > best) { best = s; bk = k; }
        }
        qidx = sknn[warp][bk];
        const float* fr = g_feats + ((size_t)b*NN + qidx) * NC;
        float* wr = g_wsel + ((size_t)gw * NL + (l + 1)) * NC;
        #pragma unroll
        for (int r = 0; r < 4; r++) wr[lane + 32*r] = fr[lane + 32*r];
    }
}

// ---------------- route + predict: 8 seqs/block, 256 thr, dynamic smem ------
// buffers: [l2][ch][8] floats (seq-minor), seq-pairs packed for f32x2.
#define RSEQ 8
#define RTPB 256
#define RBUF (6*128*RSEQ)
#define ROUTE_SMEM ((5*RBUF + 8*4*36) * 4)

__device__ __forceinline__ void mm8(const float* in, const float* __restrict__ W,
                                    const float* __restrict__ bias, float* out,
                                    int c, int g, bool doRelu) {
    unsigned long long acc[6][2];
    unsigned long long bb = packdup(bias[c]);
    #pragma unroll
    for (int l2 = 0; l2 < 6; l2++) { acc[l2][0] = bb; acc[l2][1] = bb; }
    const float4* wr = (const float4*)(W + (size_t)c * 128);
    const unsigned long long* inu = (const unsigned long long*)in;
    int pbase = 2*g;
    for (int j4 = 0; j4 < 32; j4++) {
        float4 w = __ldg(&wr[j4]);
        unsigned long long w0 = packdup(w.x), w1 = packdup(w.y);
        unsigned long long w2 = packdup(w.z), w3 = packdup(w.w);
        #pragma unroll
        for (int l2 = 0; l2 < 6; l2++) {
            const unsigned long long* r0 = inu + (size_t)(l2*128 + 4*j4)*4 + pbase;
            dfma2(acc[l2][0], r0[0],  w0); dfma2(acc[l2][1], r0[1],  w0);
            dfma2(acc[l2][0], r0[4],  w1); dfma2(acc[l2][1], r0[5],  w1);
            dfma2(acc[l2][0], r0[8],  w2); dfma2(acc[l2][1], r0[9],  w2);
            dfma2(acc[l2][0], r0[12], w3); dfma2(acc[l2][1], r0[13], w3);
        }
    }
    #pragma unroll
    for (int l2 = 0; l2 < 6; l2++) {
        #pragma unroll
        for (int pp = 0; pp < 2; pp++) {
            float v0, v1;
            unpack2(acc[l2][pp], v0, v1);
            if (doRelu) { v0 = fmaxf(v0, 0.f); v1 = fmaxf(v1, 0.f); }
            out[(l2*128 + c)*8 + (pbase + pp)*2 + 0] = v0;
            out[(l2*128 + c)*8 + (pbase + pp)*2 + 1] = v1;
        }
    }
}

__global__ __launch_bounds__(RTPB)
void route_kernel(const float* __restrict__ w_in, const float* __restrict__ b_in,
                  const float* __restrict__ w_out, const float* __restrict__ b_out,
                  const float* __restrict__ rt_w1, const float* __restrict__ rt_b1,
                  const float* __restrict__ rt_w2, const float* __restrict__ rt_b2,
                  const float* __restrict__ pw1, const float* __restrict__ pb1,
                  const float* __restrict__ pw2, const float* __restrict__ pb2,
                  int curBuf, int prevBuf) {
    extern __shared__ float sdyn[];
    float* xin = sdyn;
    float* pin = sdyn + RBUF;
    float* qs  = sdyn + 2*RBUF;
    float* ks  = sdyn + 3*RBUF;
    float* vs  = sdyn + 4*RBUF;
    float* sc  = sdyn + 5*RBUF;   // [s][h][lq][lk] = ((s*4+h)*6+lq)*6+lk
    int tid = threadIdx.x;
    int c = tid & 127, g = tid >> 7;
    size_t seq0 = (size_t)blockIdx.x * RSEQ;
    const float* curr = g_wsel;
    const float* prev = (prevBuf < 0) ? g_wsel : g_rout[prevBuf];
    for (int i = tid; i < RBUF; i += RTPB) {
        int s = i & 7, r = i >> 3;
        xin[i] = curr[(seq0 + s)*768 + r];
        pin[i] = prev[(seq0 + s)*768 + r];
    }
    __syncthreads();
    mm8(xin, w_in,            b_in,        qs, c, g, false);
    mm8(pin, w_in + 128*128,  b_in + 128,  ks, c, g, false);
    mm8(pin, w_in + 256*128,  b_in + 256,  vs, c, g, false);
    __syncthreads();
    int warp = tid >> 5, lane = tid & 31;
    for (int pp = warp; pp < 32; pp += 8) {
        int s = pp >> 2, h = pp & 3;
        for (int e = lane; e < 36; e += 32) {
            int lq = e / 6, lk = e % 6;
            float d = 0.f;
            #pragma unroll
            for (int dd = 0; dd < 32; dd++)
                d += qs[(lq*128 + h*32 + dd)*8 + s] * ks[(lk*128 + h*32 + dd)*8 + s];
            sc[((s*4 + h)*6 + lq)*6 + lk] = d / 5.656854249492381f;
        }
        __syncwarp();
        if (lane < 6) {
            float* row = &sc[((s*4 + h)*6 + lane)*6];
            float mx = -CUDART_INF_F;
            #pragma unroll
            for (int j = 0; j < 6; j++) mx = fmaxf(mx, row[j]);
            float exv[6]; float sum = 0.f;
            #pragma unroll
            for (int j = 0; j < 6; j++) { exv[j] = expf(row[j] - mx); sum += exv[j]; }
            #pragma unroll
            for (int j = 0; j < 6; j++) row[j] = exv[j] / sum;
        }
        __syncwarp();
        for (int lq = 0; lq < 6; lq++) {
            float o = 0.f;
            #pragma unroll
            for (int j = 0; j < 6; j++)
                o += sc[((s*4 + h)*6 + lq)*6 + j] * vs[(j*128 + h*32 + lane)*8 + s];
            xin[(lq*128 + h*32 + lane)*8 + s] = o;
        }
    }
    __syncthreads();
    mm8(xin, w_out, b_out, pin, c, g, false);
    __syncthreads();
    mm8(pin, rt_w1, rt_b1, qs, c, g, true);
    __syncthreads();
    mm8(qs, rt_w2, rt_b2, ks, c, g, false);
    __syncthreads();
    float* dst = g_rout[curBuf] + seq0*768;
    for (int i = tid; i < RBUF; i += RTPB) {
        int s = i & 7, r = i >> 3;
        dst[(size_t)s*768 + r] = ks[i];
    }
    // ---- fused predict head ----
    float* xv = qs;    // [8][256]
    float* hv = vs;    // [8][64]
    for (int i = tid; i < 8*128; i += RTPB) {
        int s = i >> 7, ch = i & 127;
        float cent = ks[(0*128 + ch)*8 + s];
        float sum = 0.f;
        #pragma unroll
        for (int l2 = 1; l2 < 6; l2++) sum += (ks[(l2*128 + ch)*8 + s] - cent);
        xv[s*256 + ch]       = sum * (1.0f / 5.0f);
        xv[s*256 + 128 + ch] = cent;
    }
    __syncthreads();
    for (int i = tid; i < 8*64; i += RTPB) {
        int s = i >> 6, j = i & 63;
        float acc = pb1[j];
        const float4* wr = (const float4*)(pw1 + (size_t)j * 256);
        const float4* xr = (const float4*)(xv + s*256);
        #pragma unroll 8
        for (int j4 = 0; j4 < 64; j4++) {
            float4 wv = wr[j4];
            float4 x4 = xr[j4];
            acc += wv.x*x4.x + wv.y*x4.y + wv.z*x4.z + wv.w*x4.w;
        }
        hv[s*64 + j] = fmaxf(acc, 0.f);
    }
    __syncthreads();
    if (tid < 24) {
        int s = tid / 3, o = tid % 3;
        float acc = pb2[o];
        const float* wr = pw2 + o * 64;
        const float* hh = hv + s*64;
        #pragma unroll 8
        for (int j = 0; j < 64; j++) acc += wr[j] * hh[j];
        g_disp[(seq0 + s)*3 + o] = tanhf(acc);
    }
}

// ---------------- deterministic duplicate-aware scatter-add -----------------
__global__ void scatter_kernel(const int* __restrict__ start) {
    int gid = blockIdx.x * blockDim.x + threadIdx.x;
    bbox_reset(gid);
    if (gid >= NB*NM) return;
    int b = gid >> 9, m = gid & 511;
    int n = start[gid];
    const int* sb = start + b * NM;
    for (int j = 0; j < m; j++) if (sb[j] == n) return;
    float sx = 0.f, sy = 0.f, sz = 0.f;
    for (int j = m; j < NM; j++) {
        if (sb[j] == n) {
            const float* d = g_disp + (size_t)(b*NM + j) * 3;
            sx += d[0]; sy += d[1]; sz += d[2];
        }
    }
    float* p = g_pos4 + ((size_t)b*NN + n) * 4;
    p[0] += sx; p[1] += sy; p[2] += sz;
}

__global__ void finalize_kernel(float* __restrict__ out) {
    int i = blockIdx.x * blockDim.x + threadIdx.x;
    if (i < NB*NN) {
        out[i*3+0] = g_pos4[(size_t)i*4+0];
        out[i*3+1] = g_pos4[(size_t)i*4+1];
        out[i*3+2] = g_pos4[(size_t)i*4+2];
    }
}

// ---------------- host driver ----------------------------------------------
extern "C" void kernel_launch(void* const* d_in, const int* in_sizes, int n_in,
                              void* d_out, int out_size) {
    (void)in_sizes; (void)n_in; (void)out_size;
    const float* xyz      = (const float*)d_in[0];
    const int*   start    = (const int*)  d_in[1];
    const float* gumbel   = (const float*)d_in[2];
    const float* enc_w1   = (const float*)d_in[3];
    const float* enc_b1   = (const float*)d_in[4];
    const float* enc_w2   = (const float*)d_in[5];
    const float* enc_b2   = (const float*)d_in[6];
    const float* beta_w   = (const float*)d_in[7];
    const float* beta_b   = (const float*)d_in[8];
    const float* gamma_w  = (const float*)d_in[9];
    const float* gamma_b  = (const float*)d_in[10];
    const float* attn_w_in  = (const float*)d_in[11];
    const float* attn_b_in  = (const float*)d_in[12];
    const float* attn_w_out = (const float*)d_in[13];
    const float* attn_b_out = (const float*)d_in[14];
    const float* rt_w1    = (const float*)d_in[15];
    const float* rt_b1    = (const float*)d_in[16];
    const float* rt_w2    = (const float*)d_in[17];
    const float* rt_b2    = (const float*)d_in[18];
    const float* pred_w1  = (const float*)d_in[19];
    const float* pred_b1  = (const float*)d_in[20];
    const float* pred_w2  = (const float*)d_in[21];
    const float* pred_b2  = (const float*)d_in[22];

    cudaFuncSetAttribute(route_kernel,
                         cudaFuncAttributeMaxDynamicSharedMemorySize, ROUTE_SMEM);

    init_pos_kernel<<<(NB*NN + 127)/128, 128>>>(xyz);
    encode_kernel<<<NB*NN/4, 128>>>(xyz, enc_w1, enc_b1, enc_w2, enc_b2);
    proj_kernel<<<NB*NN/16, 128>>>(beta_w, beta_b, gamma_w, gamma_b);

    for (int t = 0; t < NSTEPS; t++) {
        int cur = t & 1;
        int prv = (t == 0) ? -1 : (1 - cur);
        gridprep_kernel<<<256, 256>>>();
        hist_kernel<<<256, 256>>>();
        scan_kernel<<<NB, 1024>>>();
        scatterpts_kernel<<<256, 256>>>();
        chunkbb_kernel<<<128, 256>>>();
        knn_step_kernel<<<NB*NM/KWPB, 256>>>(start, gumbel, t);
        route_kernel<<<NB*NM/RSEQ, RTPB, ROUTE_SMEM>>>(
            attn_w_in, attn_b_in, attn_w_out, attn_b_out,
            rt_w1, rt_b1, rt_w2, rt_b2,
            pred_w1, pred_b1, pred_w2, pred_b2, cur, prv);
        scatter_kernel<<<(NB*NM + 127)/128, 128>>>(start);
    }
    finalize_kernel<<<(NB*NN + 127)/128, 128>>>((float*)d_out);
}